// round 2
// baseline (speedup 1.0000x reference)
#include <cuda_runtime.h>
#include <cstdint>

// ---------------- shapes (fixed by the problem) ----------------
#define EV   300      // embedding dim
#define EPV  150      // e-pairs
#define AP   32       // aspects padded to 32
#define TEP  30       // e-pairs per W tile
#define NT   5        // tiles (5*30 = 150)
#define WP   31       // smem W row pitch in ULL (30 used + 1 pad)

// ---------------- static device scratch ----------------
__device__ float g_ctable[50048];
__device__ unsigned long long g_aP[EPV * AP];  // (a[2ep][j], a[2ep+1][j]) packed f32x2
__device__ float g_thr[AP];                    // 0.2 * ||a_j||   (3e38 pad)
__device__ float g_waon[AP];                   // w_j / ||a_j||

__device__ __forceinline__ float2 u2f(unsigned long long v) {
    float2 r;
    asm("mov.b64 {%0,%1}, %2;" : "=f"(r.x), "=f"(r.y) : "l"(v));
    return r;
}

// ---------------- init: aspect norms + paired transpose ----------------
__global__ void init_kernel(const float* __restrict__ a_emb,
                            const float* __restrict__ a_w,
                            int A, int Edim) {
    int tid = threadIdx.x, lane = tid & 31, w = tid >> 5;
    if (w < AP) {   // one warp per (padded) aspect
        float s = 0.f;
        if (w < A)
            for (int e = lane; e < Edim; e += 32) { float v = a_emb[w * Edim + e]; s = fmaf(v, v, s); }
#pragma unroll
        for (int o = 16; o; o >>= 1) s += __shfl_xor_sync(0xffffffffu, s, o);
        if (lane == 0) {
            if (w < A) { float an = fmaxf(sqrtf(s), 1e-8f); g_thr[w] = 0.2f * an; g_waon[w] = a_w[w] / an; }
            else       { g_thr[w] = 3.0e38f; g_waon[w] = 0.f; }
        }
    }
    for (int i = tid; i < EPV * AP; i += blockDim.x) {
        int ep = i >> 5, j = i & 31;
        float lo = 0.f, hi = 0.f;
        if (j < A) { lo = a_emb[j * Edim + 2 * ep]; hi = a_emb[j * Edim + 2 * ep + 1]; }
        unsigned long long p;
        asm("mov.b64 %0, {%1,%2};" : "=l"(p) : "f"(lo), "f"(hi));
        g_aP[i] = p;
    }
}

// ---------------- vocab kernel: C[v] = max_a thresholded weighted sim ----------------
// smem: s_a[4800 ULL] aspects, s_w[128*31 ULL] W tile  -> 70144 B dynamic
extern __shared__ unsigned long long v_smem[];

__global__ __launch_bounds__(128) void vocab_kernel(const float* __restrict__ w_emb, int V) {
    unsigned long long* s_a = v_smem;
    unsigned long long* s_w = v_smem + EPV * AP;
    int tid = threadIdx.x;

    // stage aspect pairs (38.4 KB) once
    for (int i = tid; i < EPV * AP / 2; i += 128)
        ((ulonglong2*)s_a)[i] = ((const ulonglong2*)g_aP)[i];

    int row0 = blockIdx.x * 128;
    int row  = row0 + tid;
    const unsigned long long* wg = (const unsigned long long*)w_emb;  // 150 ULL per row

    unsigned long long acc[32];
#pragma unroll
    for (int j = 0; j < 32; j++) acc[j] = 0ull;
    unsigned long long accn = 0ull;

#pragma unroll 1
    for (int t = 0; t < NT; t++) {
        __syncthreads();
        // coalesced cooperative tile load: flat k = r*30 + u, warp reads consecutive ULLs
#pragma unroll
        for (int i = 0; i < TEP; i++) {
            int k = tid + i * 128;
            int r = k / TEP;
            int u = k - r * TEP;
            int gr = row0 + r;
            unsigned long long v = 0ull;
            if (gr < V) v = wg[(size_t)gr * EPV + t * TEP + u];
            s_w[r * WP + u] = v;
        }
        __syncthreads();

        const unsigned long long* wrow = s_w + tid * WP;
#pragma unroll 2
        for (int u = 0; u < TEP; u++) {
            unsigned long long w2 = wrow[u];                        // (w[2e], w[2e+1])
            asm("fma.rn.f32x2 %0, %1, %1, %0;" : "+l"(accn) : "l"(w2));
            const ulonglong2* ap = (const ulonglong2*)(s_a + (size_t)(t * TEP + u) * AP);
#pragma unroll
            for (int q = 0; q < 16; q++) {
                ulonglong2 a2 = ap[q];                              // aspects 2q, 2q+1
                asm("fma.rn.f32x2 %0, %1, %2, %0;" : "+l"(acc[2 * q])     : "l"(w2), "l"(a2.x));
                asm("fma.rn.f32x2 %0, %1, %2, %0;" : "+l"(acc[2 * q + 1]) : "l"(w2), "l"(a2.y));
            }
        }
    }

    float2 nf = u2f(accn);
    float nx = fmaxf(sqrtf(nf.x + nf.y), 1e-8f);
    float best = 0.f;
#pragma unroll
    for (int j = 0; j < 30; j++) {
        float2 d = u2f(acc[j]);
        float dot = d.x + d.y;
        if (dot > g_thr[j] * nx) best = fmaxf(best, dot * g_waon[j]);
    }
    if (row < V) g_ctable[row] = best / nx;
}

// ---------------- row kernel (unchanged, 8.2us) ----------------
__global__ __launch_bounds__(256) void row_kernel(const int* __restrict__ tokens,
                                                  const float* __restrict__ w_emb,
                                                  float* __restrict__ enc,
                                                  float* __restrict__ attn,
                                                  float* __restrict__ cscore,
                                                  int L, int E) {
    int b = blockIdx.x;
    int l = threadIdx.x;
    int lane = l & 31, wid = l >> 5;

    __shared__ float red_m[8], red_s[8];
    __shared__ int   red_n[8];
    __shared__ float bc_max, bc_cs, bc_den;
    __shared__ int   s_woff[8], s_n;
    __shared__ int   s_tok[256];
    __shared__ float s_w[256];

    int tok   = tokens[(size_t)b * L + l];
    float c   = g_ctable[tok];
    float score = (c > 0.f) ? c : -1e9f;
    int   cnt = (tok != 0) ? 1 : 0;

    float m = score, sc = c; int cn = cnt;
#pragma unroll
    for (int o = 16; o; o >>= 1) {
        m  = fmaxf(m, __shfl_xor_sync(0xffffffffu, m, o));
        sc += __shfl_xor_sync(0xffffffffu, sc, o);
        cn += __shfl_xor_sync(0xffffffffu, cn, o);
    }
    if (lane == 0) { red_m[wid] = m; red_s[wid] = sc; red_n[wid] = cn; }
    __syncthreads();
    if (l == 0) {
        float M = red_m[0], S = red_s[0]; int N = red_n[0];
#pragma unroll
        for (int i = 1; i < 8; i++) { M = fmaxf(M, red_m[i]); S += red_s[i]; N += red_n[i]; }
        bc_max = M;
        bc_cs  = S / ((float)N + 1e-5f);
    }
    __syncthreads();

    float M  = bc_max;
    float cs = bc_cs;
    float e  = expf(score - M);

    float se = e;
#pragma unroll
    for (int o = 16; o; o >>= 1) se += __shfl_xor_sync(0xffffffffu, se, o);
    if (lane == 0) red_s[wid] = se;
    __syncthreads();
    if (l == 0) {
        float D = red_s[0];
#pragma unroll
        for (int i = 1; i < 8; i++) D += red_s[i];
        bc_den = D;
    }
    __syncthreads();

    float a = e / bc_den;
    attn[(size_t)b * L + l] = a;
    if (l == 0) cscore[b] = cs;

    bool gate = cs > 1e-4f;
    if (gate) {
        bool act = (e > 0.f);
        unsigned mask = __ballot_sync(0xffffffffu, act);
        if (lane == 0) s_woff[wid] = __popc(mask);
        __syncthreads();
        if (l == 0) {
            int o = 0;
#pragma unroll
            for (int i = 0; i < 8; i++) { int t = s_woff[i]; s_woff[i] = o; o += t; }
            s_n = o;
        }
        __syncthreads();
        if (act) {
            int pos = s_woff[wid] + __popc(mask & ((1u << lane) - 1u));
            s_tok[pos] = tok;
            s_w[pos]   = a;
        }
        __syncthreads();
        int n = s_n;
        for (int j = l; j < E; j += 256) {
            float z = 0.f;
            for (int i = 0; i < n; i++)
                z = fmaf(s_w[i], w_emb[(size_t)s_tok[i] * E + j], z);
            enc[(size_t)b * E + j] = z;
        }
    } else {
        for (int j = l; j < E; j += 256)
            enc[(size_t)b * E + j] = 0.f;
    }
}

// ---------------- launch ----------------
extern "C" void kernel_launch(void* const* d_in, const int* in_sizes, int n_in,
                              void* d_out, int out_size) {
    const int*   inputs = (const int*)d_in[0];     // [B, L]
    const float* w_emb  = (const float*)d_in[1];   // [V, E]
    const float* a_emb  = (const float*)d_in[2];   // [A, E]
    const float* a_w    = (const float*)d_in[3];   // [A]

    int BL = in_sizes[0];
    int A  = in_sizes[3];
    int E  = in_sizes[2] / A;        // 300
    int V  = in_sizes[1] / E;        // 50000
    int L  = 256;
    int B  = BL / L;                 // 1024

    static bool attr_set = false;
    if (!attr_set) {
        cudaFuncSetAttribute(vocab_kernel, cudaFuncAttributeMaxDynamicSharedMemorySize,
                             (EPV * AP + 128 * WP) * 8);
        attr_set = true;
    }

    init_kernel<<<1, 1024>>>(a_emb, a_w, A, E);
    vocab_kernel<<<(V + 127) / 128, 128, (EPV * AP + 128 * WP) * 8>>>(w_emb, V);

    float* out    = (float*)d_out;
    float* enc    = out;                                   // [B, E]
    float* attn   = out + (size_t)B * E;                   // [B, L]
    float* cscore = out + (size_t)B * E + (size_t)B * L;   // [B]
    row_kernel<<<B, 256>>>(inputs, w_emb, enc, attn, cscore, L, E);
}

// round 3
// speedup vs baseline: 1.0228x; 1.0228x over previous
#include <cuda_runtime.h>
#include <cstdint>

#define EPV 150     // e-pairs (E=300)
#define AN  30      // aspects

// ---------------- static device scratch ----------------
__device__ float g_ctable[50048];
__device__ __align__(16) unsigned long long g_aP[EPV * AN]; // (a[2ep][j], a[2ep+1][j]) f32x2, pitch 30
__device__ float g_thr[AN];    // 0.2 * ||a_j||
__device__ float g_waon[AN];   // w_j / ||a_j||

__device__ __forceinline__ unsigned long long packf2(float a, float b) {
    unsigned long long r;
    asm("mov.b64 %0, {%1,%2};" : "=l"(r) : "f"(a), "f"(b));
    return r;
}
__device__ __forceinline__ float2 u2f(unsigned long long v) {
    float2 r;
    asm("mov.b64 {%0,%1}, %2;" : "=f"(r.x), "=f"(r.y) : "l"(v));
    return r;
}

// ---------------- init: parallel aspect norms + paired transpose ----------------
__global__ __launch_bounds__(256) void init_kernel(const float* __restrict__ a_emb,
                                                   const float* __restrict__ a_w,
                                                   int A, int Edim) {
    int b = blockIdx.x;
    if (b < AN) {                       // one block per aspect: norm reduction
        int j = b;
        float s = 0.f;
        if (j < A)
            for (int e = threadIdx.x; e < Edim; e += 256) {
                float v = a_emb[j * Edim + e]; s = fmaf(v, v, s);
            }
        __shared__ float red[8];
        int lane = threadIdx.x & 31, w = threadIdx.x >> 5;
#pragma unroll
        for (int o = 16; o; o >>= 1) s += __shfl_xor_sync(0xffffffffu, s, o);
        if (lane == 0) red[w] = s;
        __syncthreads();
        if (threadIdx.x == 0) {
            float t = 0.f;
#pragma unroll
            for (int i = 0; i < 8; i++) t += red[i];
            if (j < A) {
                float an = fmaxf(sqrtf(t), 1e-8f);
                g_thr[j]  = 0.2f * an;
                g_waon[j] = a_w[j] / an;
            } else { g_thr[j] = 3.0e38f; g_waon[j] = 0.f; }
        }
    } else {                            // 10 blocks fill g_aP (4500 entries)
        int base = (b - AN) * 512 + threadIdx.x * 2;
#pragma unroll
        for (int k = 0; k < 2; k++) {
            int i = base + k;
            if (i < EPV * AN) {
                int ep = i / AN, j = i - ep * AN;
                float lo = 0.f, hi = 0.f;
                if (j < A) { lo = a_emb[j * Edim + 2 * ep]; hi = a_emb[j * Edim + 2 * ep + 1]; }
                g_aP[i] = packf2(lo, hi);
            }
        }
    }
}

// ---------------- vocab kernel: C[v] = max_a thresholded weighted sim ----------------
__global__ __launch_bounds__(256) void vocab_kernel(const float* __restrict__ w_emb, int V) {
    __shared__ __align__(16) unsigned long long s_a[EPV * AN];   // 36 KB
    for (int i = threadIdx.x; i < EPV * AN / 2; i += 256)
        ((ulonglong2*)s_a)[i] = ((const ulonglong2*)g_aP)[i];
    __syncthreads();

    int row  = blockIdx.x * 256 + threadIdx.x;
    int rc   = min(row, V - 1);                       // clamp for safe loads
    const float4* wr = (const float4*)(w_emb + (size_t)rc * 300);  // 75 float4 per row

    unsigned long long acc[AN];
#pragma unroll
    for (int j = 0; j < AN; j++) acc[j] = 0ull;
    unsigned long long accn = 0ull;

    // prefetch ring, depth 4
    float4 ring[4];
#pragma unroll
    for (int d = 0; d < 4; d++) ring[d] = wr[d];

#pragma unroll 1
    for (int c = 0; c < 75; c++) {
        float4 w4 = ring[c & 3];
        if (c + 4 < 75) ring[c & 3] = wr[c + 4];
#pragma unroll
        for (int h = 0; h < 2; h++) {
            float wx = h ? w4.z : w4.x;
            float wy = h ? w4.w : w4.y;
            unsigned long long w2 = packf2(wx, wy);
            asm("fma.rn.f32x2 %0, %1, %1, %0;" : "+l"(accn) : "l"(w2));
            const ulonglong2* ap = (const ulonglong2*)(s_a + (size_t)(2 * c + h) * AN);
#pragma unroll
            for (int q = 0; q < 15; q++) {
                ulonglong2 a2 = ap[q];                // aspects 2q, 2q+1 (broadcast LDS.128)
                asm("fma.rn.f32x2 %0, %1, %2, %0;" : "+l"(acc[2 * q])     : "l"(w2), "l"(a2.x));
                asm("fma.rn.f32x2 %0, %1, %2, %0;" : "+l"(acc[2 * q + 1]) : "l"(w2), "l"(a2.y));
            }
        }
    }

    float2 nf = u2f(accn);
    float nx = fmaxf(sqrtf(nf.x + nf.y), 1e-8f);
    float best = 0.f;
#pragma unroll
    for (int j = 0; j < AN; j++) {
        float2 d = u2f(acc[j]);
        float dot = d.x + d.y;
        if (dot > g_thr[j] * nx) best = fmaxf(best, dot * g_waon[j]);
    }
    if (row < V) g_ctable[row] = best / nx;
}

// ---------------- row kernel ----------------
__global__ __launch_bounds__(256) void row_kernel(const int* __restrict__ tokens,
                                                  const float* __restrict__ w_emb,
                                                  float* __restrict__ enc,
                                                  float* __restrict__ attn,
                                                  float* __restrict__ cscore,
                                                  int L, int E) {
    int b = blockIdx.x;
    int l = threadIdx.x;
    int lane = l & 31, wid = l >> 5;

    __shared__ float red_m[8], red_s[8];
    __shared__ int   red_n[8];
    __shared__ float bc_max, bc_cs, bc_den;
    __shared__ int   s_woff[8], s_n;
    __shared__ int   s_tok[256];
    __shared__ float s_w[256];

    int tok   = tokens[(size_t)b * L + l];
    float c   = g_ctable[tok];
    float score = (c > 0.f) ? c : -1e9f;
    int   cnt = (tok != 0) ? 1 : 0;

    float m = score, sc = c; int cn = cnt;
#pragma unroll
    for (int o = 16; o; o >>= 1) {
        m  = fmaxf(m, __shfl_xor_sync(0xffffffffu, m, o));
        sc += __shfl_xor_sync(0xffffffffu, sc, o);
        cn += __shfl_xor_sync(0xffffffffu, cn, o);
    }
    if (lane == 0) { red_m[wid] = m; red_s[wid] = sc; red_n[wid] = cn; }
    __syncthreads();
    if (l == 0) {
        float M = red_m[0], S = red_s[0]; int N = red_n[0];
#pragma unroll
        for (int i = 1; i < 8; i++) { M = fmaxf(M, red_m[i]); S += red_s[i]; N += red_n[i]; }
        bc_max = M;
        bc_cs  = S / ((float)N + 1e-5f);
    }
    __syncthreads();

    float M  = bc_max;
    float cs = bc_cs;
    float e  = expf(score - M);

    float se = e;
#pragma unroll
    for (int o = 16; o; o >>= 1) se += __shfl_xor_sync(0xffffffffu, se, o);
    if (lane == 0) red_s[wid] = se;
    __syncthreads();
    if (l == 0) {
        float D = red_s[0];
#pragma unroll
        for (int i = 1; i < 8; i++) D += red_s[i];
        bc_den = D;
    }
    __syncthreads();

    float a = e / bc_den;
    attn[(size_t)b * L + l] = a;
    if (l == 0) cscore[b] = cs;

    bool gate = cs > 1e-4f;
    if (gate) {
        bool act = (e > 0.f);
        unsigned mask = __ballot_sync(0xffffffffu, act);
        if (lane == 0) s_woff[wid] = __popc(mask);
        __syncthreads();
        if (l == 0) {
            int o = 0;
#pragma unroll
            for (int i = 0; i < 8; i++) { int t = s_woff[i]; s_woff[i] = o; o += t; }
            s_n = o;
        }
        __syncthreads();
        if (act) {
            int pos = s_woff[wid] + __popc(mask & ((1u << lane) - 1u));
            s_tok[pos] = tok;
            s_w[pos]   = a;
        }
        __syncthreads();
        int n = s_n;
        for (int j = l; j < E; j += 256) {
            float z = 0.f;
            for (int i = 0; i < n; i++)
                z = fmaf(s_w[i], w_emb[(size_t)s_tok[i] * E + j], z);
            enc[(size_t)b * E + j] = z;
        }
    } else {
        for (int j = l; j < E; j += 256)
            enc[(size_t)b * E + j] = 0.f;
    }
}

// ---------------- launch ----------------
extern "C" void kernel_launch(void* const* d_in, const int* in_sizes, int n_in,
                              void* d_out, int out_size) {
    const int*   inputs = (const int*)d_in[0];     // [B, L]
    const float* w_emb  = (const float*)d_in[1];   // [V, E]
    const float* a_emb  = (const float*)d_in[2];   // [A, E]
    const float* a_w    = (const float*)d_in[3];   // [A]

    int BL = in_sizes[0];
    int A  = in_sizes[3];
    int E  = in_sizes[2] / A;        // 300
    int V  = in_sizes[1] / E;        // 50000
    int L  = 256;
    int B  = BL / L;                 // 1024

    init_kernel<<<AN + 10, 256>>>(a_emb, a_w, A, E);
    vocab_kernel<<<(V + 255) / 256, 256>>>(w_emb, V);

    float* out    = (float*)d_out;
    float* enc    = out;                                   // [B, E]
    float* attn   = out + (size_t)B * E;                   // [B, L]
    float* cscore = out + (size_t)B * E + (size_t)B * L;   // [B]
    row_kernel<<<B, 256>>>(inputs, w_emb, enc, attn, cscore, L, E);
}

// round 5
// speedup vs baseline: 1.5071x; 1.4734x over previous
#include <cuda_runtime.h>
#include <cstdint>

// ---------------- smem layout (bytes) ----------------
#define SB_B    0          // B splits: 3 x 25600 (160 k-pairs x 40 words)
#define B_SPLIT 25600
#define SB_A    76800      // A splits: 3 x 10240 (128 rows x 80B)
#define A_SPLIT 10240
#define SB_NORM 107520     // 128 floats
#define SB_THR  108032     // 32 floats
#define SB_WAON 108160     // 32 floats
#define SMEM_TOT 108288

__device__ float g_ctable[50048];

// exact 3-limb bf16 split of a pair, packed (lo=first elem)
__device__ __forceinline__ void split2pack(float x, float y,
                                           uint32_t& s0, uint32_t& s1, uint32_t& s2) {
    uint32_t ux = __float_as_uint(x), uy = __float_as_uint(y);
    float lx = x - __uint_as_float(ux & 0xffff0000u);
    float ly = y - __uint_as_float(uy & 0xffff0000u);
    uint32_t ulx = __float_as_uint(lx), uly = __float_as_uint(ly);
    float rx = lx - __uint_as_float(ulx & 0xffff0000u);
    float ry = ly - __uint_as_float(uly & 0xffff0000u);
    uint32_t urx = __float_as_uint(rx), ury = __float_as_uint(ry);
    s0 = (ux  >> 16) | (uy  & 0xffff0000u);
    s1 = (ulx >> 16) | (uly & 0xffff0000u);
    s2 = (urx >> 16) | (ury & 0xffff0000u);
}

__device__ __forceinline__ void mma16816(float* d, const uint32_t* a, const uint32_t* b) {
    asm volatile(
        "mma.sync.aligned.m16n8k16.row.col.f32.bf16.bf16.f32 "
        "{%0,%1,%2,%3}, {%4,%5,%6,%7}, {%8,%9}, {%0,%1,%2,%3};"
        : "+f"(d[0]), "+f"(d[1]), "+f"(d[2]), "+f"(d[3])
        : "r"(a[0]), "r"(a[1]), "r"(a[2]), "r"(a[3]), "r"(b[0]), "r"(b[1]));
}

// ---------------- vocab GEMM (HMMA) ----------------
__global__ __launch_bounds__(256, 2) void vocab_mma(const float* __restrict__ w_emb,
                                                    const float* __restrict__ a_emb,
                                                    const float* __restrict__ a_wt,
                                                    int V) {
    extern __shared__ char smem[];
    const int tid = threadIdx.x, lane = tid & 31, wid = tid >> 5;
    const int q = lane & 7, jrow = lane >> 3;       // loader mapping
    const int g = lane >> 2, t = lane & 3;          // mma fragment mapping

    // 1) zero B splits
    for (int i = tid; i < 3 * B_SPLIT / 16; i += 256)
        *(uint4*)(smem + SB_B + i * 16) = make_uint4(0, 0, 0, 0);
    // 2) init thr/waon pads
    if (tid < 32) {
        *(float*)(smem + SB_THR + tid * 4) = 3.0e38f;
        *(float*)(smem + SB_WAON + tid * 4) = 0.f;
    }
    __syncthreads();

    // 3) fill B (aspects): element (k=e, n=j) -> [k/2][40w] pairs, 3 splits
    for (int idx = tid; idx < 30 * 300; idx += 256) {
        int j = idx / 300, e = idx - j * 300;
        float f = a_emb[idx];
        uint32_t u = __float_as_uint(f);
        float lo = f - __uint_as_float(u & 0xffff0000u);
        uint32_t ul = __float_as_uint(lo);
        float r = lo - __uint_as_float(ul & 0xffff0000u);
        uint32_t ur = __float_as_uint(r);
        uint32_t base = (uint32_t)((e >> 1) * 160 + j * 4 + (e & 1) * 2);
        *(uint16_t*)(smem + SB_B + base)              = (uint16_t)(u  >> 16);
        *(uint16_t*)(smem + SB_B + B_SPLIT + base)    = (uint16_t)(ul >> 16);
        *(uint16_t*)(smem + SB_B + 2 * B_SPLIT + base) = (uint16_t)(ur >> 16);
    }

    // 4) aspect norms -> thr/waon (8 lanes per aspect)
    {
        int j = tid >> 3, e8 = tid & 7;
        int jj = (j < 30) ? j : 0;
        float s = 0.f;
        for (int e = e8; e < 300; e += 8) { float v = a_emb[jj * 300 + e]; s = fmaf(v, v, s); }
        s += __shfl_xor_sync(0xffffffffu, s, 1);
        s += __shfl_xor_sync(0xffffffffu, s, 2);
        s += __shfl_xor_sync(0xffffffffu, s, 4);
        if (j < 30 && e8 == 0) {
            float an = fmaxf(sqrtf(s), 1e-8f);
            *(float*)(smem + SB_THR + j * 4)  = 0.2f * an;
            *(float*)(smem + SB_WAON + j * 4) = a_wt[j] / an;
        }
    }

    // 5) preload chunk 0 (4 rows/thread-step, 128B contiguous per row)
    const float4* g4 = (const float4*)w_emb;
    int rowi[4]; bool rok[4];
    float4 buf[4];
#pragma unroll
    for (int s = 0; s < 4; s++) {
        rowi[s] = wid * 16 + s * 4 + jrow;
        int gr = blockIdx.x * 128 + rowi[s];
        rok[s] = gr < V;
        buf[s] = rok[s] ? g4[(size_t)gr * 75 + q] : make_float4(0.f, 0.f, 0.f, 0.f);
    }
    float nrm[4] = {0.f, 0.f, 0.f, 0.f};
    float d[4][4];
#pragma unroll
    for (int nt = 0; nt < 4; nt++)
#pragma unroll
        for (int i = 0; i < 4; i++) d[nt][i] = 0.f;

    __syncthreads();

    const uint32_t aWarp = SB_A + (uint32_t)(wid * 16 + g) * 80 + (uint32_t)(2 * t) * 2;

#pragma unroll 1
    for (int c = 0; c < 10; c++) {
        // convert + store current chunk
#pragma unroll
        for (int s = 0; s < 4; s++) {
            float4 v = buf[s];
            nrm[s] = fmaf(v.x, v.x, nrm[s]);
            nrm[s] = fmaf(v.y, v.y, nrm[s]);
            nrm[s] = fmaf(v.z, v.z, nrm[s]);
            nrm[s] = fmaf(v.w, v.w, nrm[s]);
            uint32_t p0a, p1a, p2a, p0b, p1b, p2b;
            split2pack(v.x, v.y, p0a, p1a, p2a);
            split2pack(v.z, v.w, p0b, p1b, p2b);
            uint32_t ro = (uint32_t)(rowi[s] * 80 + q * 8);
            *(uint2*)(smem + SB_A + ro)               = make_uint2(p0a, p0b);
            *(uint2*)(smem + SB_A + A_SPLIT + ro)     = make_uint2(p1a, p1b);
            *(uint2*)(smem + SB_A + 2 * A_SPLIT + ro) = make_uint2(p2a, p2b);
        }
        __syncthreads();

        // prefetch next chunk
        if (c < 9) {
            int qq = (c + 1) * 8 + q;
            bool qok = qq < 75;
#pragma unroll
            for (int s = 0; s < 4; s++) {
                int gr = blockIdx.x * 128 + rowi[s];
                buf[s] = (rok[s] && qok) ? g4[(size_t)gr * 75 + qq]
                                         : make_float4(0.f, 0.f, 0.f, 0.f);
            }
        }

        // MMA phase: 2 k16 steps
#pragma unroll
        for (int kk = 0; kk < 2; kk++) {
            int k16 = c * 2 + kk;
            uint32_t bf[3][4][2];
#pragma unroll
            for (int s = 0; s < 3; s++) {
                uint32_t sbase = SB_B + (uint32_t)s * B_SPLIT +
                                 (uint32_t)(k16 * 8 + t) * 160 + (uint32_t)g * 4;
#pragma unroll
                for (int nt = 0; nt < 4; nt++) {
                    bf[s][nt][0] = *(const uint32_t*)(smem + sbase + nt * 32);
                    bf[s][nt][1] = *(const uint32_t*)(smem + sbase + nt * 32 + 640);
                }
            }
            uint32_t af[3][4];
#pragma unroll
            for (int s = 0; s < 3; s++) {
                uint32_t ab = aWarp + (uint32_t)s * A_SPLIT + (uint32_t)(kk * 16) * 2;
                af[s][0] = *(const uint32_t*)(smem + ab);
                af[s][1] = *(const uint32_t*)(smem + ab + 640);
                af[s][2] = *(const uint32_t*)(smem + ab + 16);
                af[s][3] = *(const uint32_t*)(smem + ab + 656);
            }
#pragma unroll
            for (int nt = 0; nt < 4; nt++) {
                mma16816(d[nt], af[0], bf[0][nt]);   // w0*a0
                mma16816(d[nt], af[0], bf[1][nt]);   // w0*a1
                mma16816(d[nt], af[1], bf[0][nt]);   // w1*a0
                mma16816(d[nt], af[0], bf[2][nt]);   // w0*a2
                mma16816(d[nt], af[2], bf[0][nt]);   // w2*a0
                mma16816(d[nt], af[1], bf[1][nt]);   // w1*a1
            }
        }
        __syncthreads();
    }

    // norms -> smem (sum over the 8 q-lanes)
#pragma unroll
    for (int s = 0; s < 4; s++) {
        float n = nrm[s];
        n += __shfl_xor_sync(0xffffffffu, n, 1);
        n += __shfl_xor_sync(0xffffffffu, n, 2);
        n += __shfl_xor_sync(0xffffffffu, n, 4);
        if (q == 0) *(float*)(smem + SB_NORM + rowi[s] * 4) = n;
    }
    __syncthreads();

    // epilogue: threshold + max over aspects
    int r0 = wid * 16 + g, r1 = r0 + 8;
    float nx0 = fmaxf(sqrtf(*(const float*)(smem + SB_NORM + r0 * 4)), 1e-8f);
    float nx1 = fmaxf(sqrtf(*(const float*)(smem + SB_NORM + r1 * 4)), 1e-8f);
    float b0 = 0.f, b1 = 0.f;
#pragma unroll
    for (int nt = 0; nt < 4; nt++) {
        int j0 = nt * 8 + 2 * t, j1 = j0 + 1;
        float th0 = *(const float*)(smem + SB_THR + j0 * 4);
        float th1 = *(const float*)(smem + SB_THR + j1 * 4);
        float w0  = *(const float*)(smem + SB_WAON + j0 * 4);
        float w1  = *(const float*)(smem + SB_WAON + j1 * 4);
        if (d[nt][0] > th0 * nx0) b0 = fmaxf(b0, d[nt][0] * w0);
        if (d[nt][1] > th1 * nx0) b0 = fmaxf(b0, d[nt][1] * w1);
        if (d[nt][2] > th0 * nx1) b1 = fmaxf(b1, d[nt][2] * w0);
        if (d[nt][3] > th1 * nx1) b1 = fmaxf(b1, d[nt][3] * w1);
    }
    b0 = fmaxf(b0, __shfl_xor_sync(0xffffffffu, b0, 1));
    b0 = fmaxf(b0, __shfl_xor_sync(0xffffffffu, b0, 2));
    b1 = fmaxf(b1, __shfl_xor_sync(0xffffffffu, b1, 1));
    b1 = fmaxf(b1, __shfl_xor_sync(0xffffffffu, b1, 2));
    if (t == 0) {
        int o0 = blockIdx.x * 128 + r0;
        int o1 = blockIdx.x * 128 + r1;
        if (o0 < V) g_ctable[o0] = b0 / nx0;
        if (o1 < V) g_ctable[o1] = b1 / nx1;
    }
}

// ---------------- row kernel ----------------
__global__ __launch_bounds__(256) void row_kernel(const int* __restrict__ tokens,
                                                  const float* __restrict__ w_emb,
                                                  float* __restrict__ enc,
                                                  float* __restrict__ attn,
                                                  float* __restrict__ cscore,
                                                  int L, int E) {
    int b = blockIdx.x;
    int l = threadIdx.x;
    int lane = l & 31, wid = l >> 5;

    __shared__ float red_m[8], red_s[8];
    __shared__ int   red_n[8];
    __shared__ float bc_max, bc_cs, bc_den;
    __shared__ int   s_woff[8], s_n;
    __shared__ int   s_tok[256];
    __shared__ float s_w[256];

    int tok   = tokens[(size_t)b * L + l];
    float c   = g_ctable[tok];
    float score = (c > 0.f) ? c : -1e9f;
    int   cnt = (tok != 0) ? 1 : 0;

    float m = score, sc = c; int cn = cnt;
#pragma unroll
    for (int o = 16; o; o >>= 1) {
        m  = fmaxf(m, __shfl_xor_sync(0xffffffffu, m, o));
        sc += __shfl_xor_sync(0xffffffffu, sc, o);
        cn += __shfl_xor_sync(0xffffffffu, cn, o);
    }
    if (lane == 0) { red_m[wid] = m; red_s[wid] = sc; red_n[wid] = cn; }
    __syncthreads();
    if (l == 0) {
        float M = red_m[0], S = red_s[0]; int N = red_n[0];
#pragma unroll
        for (int i = 1; i < 8; i++) { M = fmaxf(M, red_m[i]); S += red_s[i]; N += red_n[i]; }
        bc_max = M;
        bc_cs  = S / ((float)N + 1e-5f);
    }
    __syncthreads();

    float M  = bc_max;
    float cs = bc_cs;
    float e  = expf(score - M);

    float se = e;
#pragma unroll
    for (int o = 16; o; o >>= 1) se += __shfl_xor_sync(0xffffffffu, se, o);
    if (lane == 0) red_s[wid] = se;
    __syncthreads();
    if (l == 0) {
        float D = red_s[0];
#pragma unroll
        for (int i = 1; i < 8; i++) D += red_s[i];
        bc_den = D;
    }
    __syncthreads();

    float a = e / bc_den;
    attn[(size_t)b * L + l] = a;
    if (l == 0) cscore[b] = cs;

    bool gate = cs > 1e-4f;
    if (gate) {
        bool act = (e > 0.f);
        unsigned mask = __ballot_sync(0xffffffffu, act);
        if (lane == 0) s_woff[wid] = __popc(mask);
        __syncthreads();
        if (l == 0) {
            int o = 0;
#pragma unroll
            for (int i = 0; i < 8; i++) { int tt = s_woff[i]; s_woff[i] = o; o += tt; }
            s_n = o;
        }
        __syncthreads();
        if (act) {
            int pos = s_woff[wid] + __popc(mask & ((1u << lane) - 1u));
            s_tok[pos] = tok;
            s_w[pos]   = a;
        }
        __syncthreads();
        int n = s_n;
        for (int j = l; j < E; j += 256) {
            float z = 0.f;
            for (int i = 0; i < n; i++)
                z = fmaf(s_w[i], w_emb[(size_t)s_tok[i] * E + j], z);
            enc[(size_t)b * E + j] = z;
        }
    } else {
        for (int j = l; j < E; j += 256)
            enc[(size_t)b * E + j] = 0.f;
    }
}

// ---------------- launch ----------------
extern "C" void kernel_launch(void* const* d_in, const int* in_sizes, int n_in,
                              void* d_out, int out_size) {
    const int*   inputs = (const int*)d_in[0];     // [B, L]
    const float* w_emb  = (const float*)d_in[1];   // [V, E]
    const float* a_emb  = (const float*)d_in[2];   // [A, E]
    const float* a_w    = (const float*)d_in[3];   // [A]

    int BL = in_sizes[0];
    int A  = in_sizes[3];
    int E  = in_sizes[2] / A;        // 300
    int V  = in_sizes[1] / E;        // 50000
    int L  = 256;
    int B  = BL / L;                 // 1024

    static bool attr_set = false;
    if (!attr_set) {
        cudaFuncSetAttribute(vocab_mma, cudaFuncAttributeMaxDynamicSharedMemorySize, SMEM_TOT);
        attr_set = true;
    }

    vocab_mma<<<(V + 127) / 128, 256, SMEM_TOT>>>(w_emb, a_emb, a_w, V);

    float* out    = (float*)d_out;
    float* enc    = out;                                   // [B, E]
    float* attn   = out + (size_t)B * E;                   // [B, L]
    float* cscore = out + (size_t)B * E + (size_t)B * L;   // [B]
    row_kernel<<<B, 256>>>(inputs, w_emb, enc, attn, cscore, L, E);
}

// round 6
// speedup vs baseline: 2.0171x; 1.3384x over previous
#include <cuda_runtime.h>
#include <cuda_fp16.h>
#include <cstdint>

// ---------------- smem layout (bytes) ----------------
#define SB_B    0          // B splits: 2 x 25600 (160 k-pairs x 160B)
#define B_SPLIT 25600
#define SB_A    51200      // A splits: 2 x 10240 (128 rows x 80B)
#define A_SPLIT 10240
#define SB_NORM 71680      // 128 floats
#define SB_THR  72192      // 32 floats
#define SB_WAON 72320      // 32 floats
#define SMEM_TOT 72448

__device__ float g_ctable[50048];

__device__ __forceinline__ uint32_t h2u(__half2 h) {
    union { __half2 h; uint32_t u; } cv; cv.h = h; return cv.u;
}

// 2-limb fp16 split of a pair, packed (lo = first elem)
__device__ __forceinline__ void split2pack(float x, float y, uint32_t& s0, uint32_t& s1) {
    __half2 h0 = __float22half2_rn(make_float2(x, y));
    float2 f0 = __half22float2(h0);
    __half2 h1 = __float22half2_rn(make_float2(x - f0.x, y - f0.y));
    s0 = h2u(h0);
    s1 = h2u(h1);
}

__device__ __forceinline__ void mma16816(float* d, const uint32_t* a, const uint32_t* b) {
    asm volatile(
        "mma.sync.aligned.m16n8k16.row.col.f32.f16.f16.f32 "
        "{%0,%1,%2,%3}, {%4,%5,%6,%7}, {%8,%9}, {%0,%1,%2,%3};"
        : "+f"(d[0]), "+f"(d[1]), "+f"(d[2]), "+f"(d[3])
        : "r"(a[0]), "r"(a[1]), "r"(a[2]), "r"(a[3]), "r"(b[0]), "r"(b[1]));
}

// ---------------- vocab GEMM (HMMA, fp16 2-limb) ----------------
__global__ __launch_bounds__(256, 3) void vocab_mma(const float* __restrict__ w_emb,
                                                    const float* __restrict__ a_emb,
                                                    const float* __restrict__ a_wt,
                                                    int V) {
    extern __shared__ char smem[];
    const int tid = threadIdx.x, lane = tid & 31, wid = tid >> 5;
    const int q = lane & 7, jrow = lane >> 3;       // loader mapping
    const int g = lane >> 2, t = lane & 3;          // mma fragment mapping

    // 1) zero B splits
    for (int i = tid; i < 2 * B_SPLIT / 16; i += 256)
        *(uint4*)(smem + SB_B + i * 16) = make_uint4(0, 0, 0, 0);
    if (tid < 32) {
        *(float*)(smem + SB_THR + tid * 4) = 3.0e38f;
        *(float*)(smem + SB_WAON + tid * 4) = 0.f;
    }
    __syncthreads();

    // 2) fill B (aspects): element (k=e, n=j) -> [e/2][j*4 + (e&1)*2], 2 splits
    for (int idx = tid; idx < 30 * 300; idx += 256) {
        int j = idx / 300, e = idx - j * 300;
        float f = a_emb[idx];
        __half h0 = __float2half_rn(f);
        __half h1 = __float2half_rn(f - __half2float(h0));
        uint32_t base = (uint32_t)((e >> 1) * 160 + j * 4 + (e & 1) * 2);
        *(__half*)(smem + SB_B + base)           = h0;
        *(__half*)(smem + SB_B + B_SPLIT + base) = h1;
    }

    // 3) aspect norms -> thr/waon (8 lanes per aspect)
    {
        int j = tid >> 3, e8 = tid & 7;
        int jj = (j < 30) ? j : 0;
        float s = 0.f;
        for (int e = e8; e < 300; e += 8) { float v = a_emb[jj * 300 + e]; s = fmaf(v, v, s); }
        s += __shfl_xor_sync(0xffffffffu, s, 1);
        s += __shfl_xor_sync(0xffffffffu, s, 2);
        s += __shfl_xor_sync(0xffffffffu, s, 4);
        if (j < 30 && e8 == 0) {
            float an = fmaxf(sqrtf(s), 1e-8f);
            *(float*)(smem + SB_THR + j * 4)  = 0.2f * an;
            *(float*)(smem + SB_WAON + j * 4) = a_wt[j] / an;
        }
    }

    // 4) preload chunk 0
    const float4* g4 = (const float4*)w_emb;
    int rowi[4]; bool rok[4];
    float4 buf[4];
#pragma unroll
    for (int s = 0; s < 4; s++) {
        rowi[s] = wid * 16 + s * 4 + jrow;
        int gr = blockIdx.x * 128 + rowi[s];
        rok[s] = gr < V;
        buf[s] = rok[s] ? g4[(size_t)gr * 75 + q] : make_float4(0.f, 0.f, 0.f, 0.f);
    }
    float nrm[4] = {0.f, 0.f, 0.f, 0.f};
    float d[4][4];
#pragma unroll
    for (int nt = 0; nt < 4; nt++)
#pragma unroll
        for (int i = 0; i < 4; i++) d[nt][i] = 0.f;

    __syncthreads();

    const uint32_t aWarp = SB_A + (uint32_t)(wid * 16 + g) * 80 + (uint32_t)(2 * t) * 2;

#pragma unroll 1
    for (int c = 0; c < 10; c++) {
        // convert + store current chunk
#pragma unroll
        for (int s = 0; s < 4; s++) {
            float4 v = buf[s];
            nrm[s] = fmaf(v.x, v.x, nrm[s]);
            nrm[s] = fmaf(v.y, v.y, nrm[s]);
            nrm[s] = fmaf(v.z, v.z, nrm[s]);
            nrm[s] = fmaf(v.w, v.w, nrm[s]);
            uint32_t p0a, p1a, p0b, p1b;
            split2pack(v.x, v.y, p0a, p1a);
            split2pack(v.z, v.w, p0b, p1b);
            uint32_t ro = (uint32_t)(rowi[s] * 80 + q * 8);
            *(uint2*)(smem + SB_A + ro)           = make_uint2(p0a, p0b);
            *(uint2*)(smem + SB_A + A_SPLIT + ro) = make_uint2(p1a, p1b);
        }
        __syncthreads();

        // prefetch next chunk
        if (c < 9) {
            int qq = (c + 1) * 8 + q;
            bool qok = qq < 75;
#pragma unroll
            for (int s = 0; s < 4; s++) {
                int gr = blockIdx.x * 128 + rowi[s];
                buf[s] = (rok[s] && qok) ? g4[(size_t)gr * 75 + qq]
                                         : make_float4(0.f, 0.f, 0.f, 0.f);
            }
        }

        // MMA phase: 2 k16 steps, 3 limb products each
#pragma unroll
        for (int kk = 0; kk < 2; kk++) {
            int k16 = c * 2 + kk;
            uint32_t bf[2][4][2];
#pragma unroll
            for (int s = 0; s < 2; s++) {
                uint32_t sbase = SB_B + (uint32_t)s * B_SPLIT +
                                 (uint32_t)(k16 * 8 + t) * 160 + (uint32_t)g * 4;
#pragma unroll
                for (int nt = 0; nt < 4; nt++) {
                    bf[s][nt][0] = *(const uint32_t*)(smem + sbase + nt * 32);
                    bf[s][nt][1] = *(const uint32_t*)(smem + sbase + nt * 32 + 640);
                }
            }
            uint32_t af[2][4];
#pragma unroll
            for (int s = 0; s < 2; s++) {
                uint32_t ab = aWarp + (uint32_t)s * A_SPLIT + (uint32_t)(kk * 16) * 2;
                af[s][0] = *(const uint32_t*)(smem + ab);
                af[s][1] = *(const uint32_t*)(smem + ab + 640);
                af[s][2] = *(const uint32_t*)(smem + ab + 16);
                af[s][3] = *(const uint32_t*)(smem + ab + 656);
            }
#pragma unroll
            for (int nt = 0; nt < 4; nt++) {
                mma16816(d[nt], af[0], bf[0][nt]);   // w0*a0
                mma16816(d[nt], af[0], bf[1][nt]);   // w0*a1
                mma16816(d[nt], af[1], bf[0][nt]);   // w1*a0
            }
        }
        __syncthreads();
    }

    // norms -> smem
#pragma unroll
    for (int s = 0; s < 4; s++) {
        float n = nrm[s];
        n += __shfl_xor_sync(0xffffffffu, n, 1);
        n += __shfl_xor_sync(0xffffffffu, n, 2);
        n += __shfl_xor_sync(0xffffffffu, n, 4);
        if (q == 0) *(float*)(smem + SB_NORM + rowi[s] * 4) = n;
    }
    __syncthreads();

    // epilogue: threshold + max over aspects
    int r0 = wid * 16 + g, r1 = r0 + 8;
    float nx0 = fmaxf(sqrtf(*(const float*)(smem + SB_NORM + r0 * 4)), 1e-8f);
    float nx1 = fmaxf(sqrtf(*(const float*)(smem + SB_NORM + r1 * 4)), 1e-8f);
    float b0 = 0.f, b1 = 0.f;
#pragma unroll
    for (int nt = 0; nt < 4; nt++) {
        int j0 = nt * 8 + 2 * t, j1 = j0 + 1;
        float th0 = *(const float*)(smem + SB_THR + j0 * 4);
        float th1 = *(const float*)(smem + SB_THR + j1 * 4);
        float w0  = *(const float*)(smem + SB_WAON + j0 * 4);
        float w1  = *(const float*)(smem + SB_WAON + j1 * 4);
        if (d[nt][0] > th0 * nx0) b0 = fmaxf(b0, d[nt][0] * w0);
        if (d[nt][1] > th1 * nx0) b0 = fmaxf(b0, d[nt][1] * w1);
        if (d[nt][2] > th0 * nx1) b1 = fmaxf(b1, d[nt][2] * w0);
        if (d[nt][3] > th1 * nx1) b1 = fmaxf(b1, d[nt][3] * w1);
    }
    b0 = fmaxf(b0, __shfl_xor_sync(0xffffffffu, b0, 1));
    b0 = fmaxf(b0, __shfl_xor_sync(0xffffffffu, b0, 2));
    b1 = fmaxf(b1, __shfl_xor_sync(0xffffffffu, b1, 1));
    b1 = fmaxf(b1, __shfl_xor_sync(0xffffffffu, b1, 2));
    if (t == 0) {
        int o0 = blockIdx.x * 128 + r0;
        int o1 = blockIdx.x * 128 + r1;
        if (o0 < V) g_ctable[o0] = b0 / nx0;
        if (o1 < V) g_ctable[o1] = b1 / nx1;
    }
}

// ---------------- row kernel ----------------
__global__ __launch_bounds__(256) void row_kernel(const int* __restrict__ tokens,
                                                  const float* __restrict__ w_emb,
                                                  float* __restrict__ enc,
                                                  float* __restrict__ attn,
                                                  float* __restrict__ cscore,
                                                  int L, int E) {
    int b = blockIdx.x;
    int l = threadIdx.x;
    int lane = l & 31, wid = l >> 5;

    __shared__ float red_m[8], red_s[8];
    __shared__ int   red_n[8];
    __shared__ float bc_max, bc_cs, bc_den;
    __shared__ int   s_woff[8], s_n;
    __shared__ int   s_tok[256];
    __shared__ float s_w[256];

    int tok   = tokens[(size_t)b * L + l];
    float c   = g_ctable[tok];
    float score = (c > 0.f) ? c : -1e9f;
    int   cnt = (tok != 0) ? 1 : 0;

    float m = score, sc = c; int cn = cnt;
#pragma unroll
    for (int o = 16; o; o >>= 1) {
        m  = fmaxf(m, __shfl_xor_sync(0xffffffffu, m, o));
        sc += __shfl_xor_sync(0xffffffffu, sc, o);
        cn += __shfl_xor_sync(0xffffffffu, cn, o);
    }
    if (lane == 0) { red_m[wid] = m; red_s[wid] = sc; red_n[wid] = cn; }
    __syncthreads();
    if (l == 0) {
        float M = red_m[0], S = red_s[0]; int N = red_n[0];
#pragma unroll
        for (int i = 1; i < 8; i++) { M = fmaxf(M, red_m[i]); S += red_s[i]; N += red_n[i]; }
        bc_max = M;
        bc_cs  = S / ((float)N + 1e-5f);
    }
    __syncthreads();

    float M  = bc_max;
    float cs = bc_cs;
    float e  = expf(score - M);

    float se = e;
#pragma unroll
    for (int o = 16; o; o >>= 1) se += __shfl_xor_sync(0xffffffffu, se, o);
    if (lane == 0) red_s[wid] = se;
    __syncthreads();
    if (l == 0) {
        float D = red_s[0];
#pragma unroll
        for (int i = 1; i < 8; i++) D += red_s[i];
        bc_den = D;
    }
    __syncthreads();

    float a = e / bc_den;
    attn[(size_t)b * L + l] = a;
    if (l == 0) cscore[b] = cs;

    bool gate = cs > 1e-4f;
    if (gate) {
        bool act = (e > 0.f);
        unsigned mask = __ballot_sync(0xffffffffu, act);
        if (lane == 0) s_woff[wid] = __popc(mask);
        __syncthreads();
        if (l == 0) {
            int o = 0;
#pragma unroll
            for (int i = 0; i < 8; i++) { int tt = s_woff[i]; s_woff[i] = o; o += tt; }
            s_n = o;
        }
        __syncthreads();
        if (act) {
            int pos = s_woff[wid] + __popc(mask & ((1u << lane) - 1u));
            s_tok[pos] = tok;
            s_w[pos]   = a;
        }
        __syncthreads();
        int n = s_n;
        for (int j = l; j < E; j += 256) {
            float z = 0.f;
            for (int i = 0; i < n; i++)
                z = fmaf(s_w[i], w_emb[(size_t)s_tok[i] * E + j], z);
            enc[(size_t)b * E + j] = z;
        }
    } else {
        for (int j = l; j < E; j += 256)
            enc[(size_t)b * E + j] = 0.f;
    }
}

// ---------------- launch ----------------
extern "C" void kernel_launch(void* const* d_in, const int* in_sizes, int n_in,
                              void* d_out, int out_size) {
    const int*   inputs = (const int*)d_in[0];     // [B, L]
    const float* w_emb  = (const float*)d_in[1];   // [V, E]
    const float* a_emb  = (const float*)d_in[2];   // [A, E]
    const float* a_w    = (const float*)d_in[3];   // [A]

    int BL = in_sizes[0];
    int A  = in_sizes[3];
    int E  = in_sizes[2] / A;        // 300
    int V  = in_sizes[1] / E;        // 50000
    int L  = 256;
    int B  = BL / L;                 // 1024

    static bool attr_set = false;
    if (!attr_set) {
        cudaFuncSetAttribute(vocab_mma, cudaFuncAttributeMaxDynamicSharedMemorySize, SMEM_TOT);
        attr_set = true;
    }

    vocab_mma<<<(V + 127) / 128, 256, SMEM_TOT>>>(w_emb, a_emb, a_w, V);

    float* out    = (float*)d_out;
    float* enc    = out;                                   // [B, E]
    float* attn   = out + (size_t)B * E;                   // [B, L]
    float* cscore = out + (size_t)B * E + (size_t)B * L;   // [B]
    row_kernel<<<B, 256>>>(inputs, w_emb, enc, attn, cscore, L, E);
}

// round 7
// speedup vs baseline: 2.4412x; 1.2102x over previous
#include <cuda_runtime.h>
#include <cuda_fp16.h>
#include <cstdint>

// ---------------- smem layout (bytes) ----------------
#define SB_B    0          // B splits: 2 x 25600 (160 k-pairs x 160B)
#define B_SPLIT 25600
#define SB_THR  51200      // 32 floats
#define SB_WAON 51328      // 32 floats
#define SMEM_TOT 51456

__device__ float g_ctable[50048];

__device__ __forceinline__ uint32_t h2u(__half2 h) {
    union { __half2 h; uint32_t u; } cv; cv.h = h; return cv.u;
}

// 2-limb fp16 split of a k-consecutive pair -> two fragment words
__device__ __forceinline__ void split2pack(float2 v, uint32_t& s0, uint32_t& s1) {
    __half2 h0 = __float22half2_rn(v);
    float2 f0 = __half22float2(h0);
    __half2 h1 = __float22half2_rn(make_float2(v.x - f0.x, v.y - f0.y));
    s0 = h2u(h0);
    s1 = h2u(h1);
}

__device__ __forceinline__ void mma16816(float* d, const uint32_t* a, const uint32_t* b) {
    asm volatile(
        "mma.sync.aligned.m16n8k16.row.col.f32.f16.f16.f32 "
        "{%0,%1,%2,%3}, {%4,%5,%6,%7}, {%8,%9}, {%0,%1,%2,%3};"
        : "+f"(d[0]), "+f"(d[1]), "+f"(d[2]), "+f"(d[3])
        : "r"(a[0]), "r"(a[1]), "r"(a[2]), "r"(a[3]), "r"(b[0]), "r"(b[1]));
}

__device__ __forceinline__ float2 ldw2(const float* p, bool ok) {
    return ok ? __ldg((const float2*)p) : make_float2(0.f, 0.f);
}

// ---------------- vocab GEMM (HMMA, fp16 2-limb, direct-fragment LDG) ----------------
__global__ __launch_bounds__(256, 3) void vocab_mma(const float* __restrict__ w_emb,
                                                    const float* __restrict__ a_emb,
                                                    const float* __restrict__ a_wt,
                                                    int V) {
    extern __shared__ char smem[];
    const int tid = threadIdx.x, lane = tid & 31, wid = tid >> 5;
    const int g = lane >> 2, t = lane & 3;          // mma fragment mapping

    // 1) zero B splits + pads
    for (int i = tid; i < 2 * B_SPLIT / 16; i += 256)
        *(uint4*)(smem + SB_B + i * 16) = make_uint4(0, 0, 0, 0);
    if (tid < 32) {
        *(float*)(smem + SB_THR + tid * 4) = 3.0e38f;
        *(float*)(smem + SB_WAON + tid * 4) = 0.f;
    }
    __syncthreads();

    // 2) fill B (aspects): element (k=e, n=j) -> word (e>>1)*160 + j*4 (+2 if e odd)
    for (int idx = tid; idx < 30 * 300; idx += 256) {
        int j = idx / 300, e = idx - j * 300;
        float f = a_emb[idx];
        __half h0 = __float2half_rn(f);
        __half h1 = __float2half_rn(f - __half2float(h0));
        uint32_t base = (uint32_t)((e >> 1) * 160 + j * 4 + (e & 1) * 2);
        *(__half*)(smem + SB_B + base)           = h0;
        *(__half*)(smem + SB_B + B_SPLIT + base) = h1;
    }

    // 3) aspect norms -> thr/waon (8 lanes per aspect)
    {
        int j = tid >> 3, e8 = tid & 7;
        int jj = (j < 30) ? j : 0;
        float s = 0.f;
        for (int e = e8; e < 300; e += 8) { float v = a_emb[jj * 300 + e]; s = fmaf(v, v, s); }
        s += __shfl_xor_sync(0xffffffffu, s, 1);
        s += __shfl_xor_sync(0xffffffffu, s, 2);
        s += __shfl_xor_sync(0xffffffffu, s, 4);
        if (j < 30 && e8 == 0) {
            float an = fmaxf(sqrtf(s), 1e-8f);
            *(float*)(smem + SB_THR + j * 4)  = 0.2f * an;
            *(float*)(smem + SB_WAON + j * 4) = a_wt[j] / an;
        }
    }
    __syncthreads();

    // 4) row pointers (rows g and g+8 of this warp's m16 tile)
    const int r0 = wid * 16 + g, r1 = r0 + 8;
    const int gr0 = blockIdx.x * 128 + r0, gr1 = blockIdx.x * 128 + r1;
    const bool rok0 = gr0 < V, rok1 = gr1 < V;
    const float* p0 = w_emb + (size_t)(rok0 ? gr0 : 0) * 300 + 2 * t;
    const float* p1 = w_emb + (size_t)(rok1 ? gr1 : 0) * 300 + 2 * t;

    float d[4][4];
#pragma unroll
    for (int nt = 0; nt < 4; nt++)
#pragma unroll
        for (int i = 0; i < 4; i++) d[nt][i] = 0.f;
    float nrm0 = 0.f, nrm1 = 0.f;

    // prefetch k16 = 0
    float2 cur0 = ldw2(p0,      rok0);
    float2 cur1 = ldw2(p0 + 8,  rok0);
    float2 cur2 = ldw2(p1,      rok1);
    float2 cur3 = ldw2(p1 + 8,  rok1);

#pragma unroll 1
    for (int k16 = 0; k16 < 19; k16++) {
        // prefetch next step (hi-pair of k16==18 out of range for t>=2)
        float2 nx0, nx1, nx2, nx3;
        if (k16 < 18) {
            const float* q0 = p0 + (k16 + 1) * 16;
            const float* q1 = p1 + (k16 + 1) * 16;
            bool hok = (k16 + 1 < 18) | (t < 2);
            nx0 = ldw2(q0,     rok0);
            nx1 = ldw2(q0 + 8, rok0 & hok);
            nx2 = ldw2(q1,     rok1);
            nx3 = ldw2(q1 + 8, rok1 & hok);
        }

        // convert current fragments in-register
        uint32_t af[2][4];
        split2pack(cur0, af[0][0], af[1][0]);   // a0: row g,  k 2t,2t+1
        split2pack(cur2, af[0][1], af[1][1]);   // a1: row g+8
        split2pack(cur1, af[0][2], af[1][2]);   // a2: row g,  k 2t+8,2t+9
        split2pack(cur3, af[0][3], af[1][3]);   // a3: row g+8
        nrm0 = fmaf(cur0.x, cur0.x, nrm0); nrm0 = fmaf(cur0.y, cur0.y, nrm0);
        nrm0 = fmaf(cur1.x, cur1.x, nrm0); nrm0 = fmaf(cur1.y, cur1.y, nrm0);
        nrm1 = fmaf(cur2.x, cur2.x, nrm1); nrm1 = fmaf(cur2.y, cur2.y, nrm1);
        nrm1 = fmaf(cur3.x, cur3.x, nrm1); nrm1 = fmaf(cur3.y, cur3.y, nrm1);

        // B fragments (conflict-free LDS.32)
        uint32_t bf[2][4][2];
        uint32_t sbase = (uint32_t)((k16 * 8 + t) * 160 + g * 4);
#pragma unroll
        for (int s = 0; s < 2; s++) {
            uint32_t sb = SB_B + (uint32_t)s * B_SPLIT + sbase;
#pragma unroll
            for (int nt = 0; nt < 4; nt++) {
                bf[s][nt][0] = *(const uint32_t*)(smem + sb + nt * 32);
                bf[s][nt][1] = *(const uint32_t*)(smem + sb + nt * 32 + 640);
            }
        }

#pragma unroll
        for (int nt = 0; nt < 4; nt++) {
            mma16816(d[nt], af[0], bf[0][nt]);   // w0*a0
            mma16816(d[nt], af[0], bf[1][nt]);   // w0*a1
            mma16816(d[nt], af[1], bf[0][nt]);   // w1*a0
        }

        cur0 = nx0; cur1 = nx1; cur2 = nx2; cur3 = nx3;
    }

    // reduce norms over the 4 t-lanes
    nrm0 += __shfl_xor_sync(0xffffffffu, nrm0, 1);
    nrm0 += __shfl_xor_sync(0xffffffffu, nrm0, 2);
    nrm1 += __shfl_xor_sync(0xffffffffu, nrm1, 1);
    nrm1 += __shfl_xor_sync(0xffffffffu, nrm1, 2);
    float nx0 = fmaxf(sqrtf(nrm0), 1e-8f);
    float nx1 = fmaxf(sqrtf(nrm1), 1e-8f);

    // epilogue: threshold + max over aspects
    float b0 = 0.f, b1 = 0.f;
#pragma unroll
    for (int nt = 0; nt < 4; nt++) {
        int j0 = nt * 8 + 2 * t, j1 = j0 + 1;
        float th0 = *(const float*)(smem + SB_THR + j0 * 4);
        float th1 = *(const float*)(smem + SB_THR + j1 * 4);
        float w0  = *(const float*)(smem + SB_WAON + j0 * 4);
        float w1  = *(const float*)(smem + SB_WAON + j1 * 4);
        if (d[nt][0] > th0 * nx0) b0 = fmaxf(b0, d[nt][0] * w0);
        if (d[nt][1] > th1 * nx0) b0 = fmaxf(b0, d[nt][1] * w1);
        if (d[nt][2] > th0 * nx1) b1 = fmaxf(b1, d[nt][2] * w0);
        if (d[nt][3] > th1 * nx1) b1 = fmaxf(b1, d[nt][3] * w1);
    }
    b0 = fmaxf(b0, __shfl_xor_sync(0xffffffffu, b0, 1));
    b0 = fmaxf(b0, __shfl_xor_sync(0xffffffffu, b0, 2));
    b1 = fmaxf(b1, __shfl_xor_sync(0xffffffffu, b1, 1));
    b1 = fmaxf(b1, __shfl_xor_sync(0xffffffffu, b1, 2));
    if (t == 0) {
        if (rok0) g_ctable[gr0] = b0 / nx0;
        if (rok1) g_ctable[gr1] = b1 / nx1;
    }
}

// ---------------- row kernel ----------------
__global__ __launch_bounds__(256) void row_kernel(const int* __restrict__ tokens,
                                                  const float* __restrict__ w_emb,
                                                  float* __restrict__ enc,
                                                  float* __restrict__ attn,
                                                  float* __restrict__ cscore,
                                                  int L, int E) {
    int b = blockIdx.x;
    int l = threadIdx.x;
    int lane = l & 31, wid = l >> 5;

    __shared__ float red_m[8], red_s[8];
    __shared__ int   red_n[8];
    __shared__ float bc_max, bc_cs, bc_den;
    __shared__ int   s_woff[8], s_n;
    __shared__ int   s_tok[256];
    __shared__ float s_w[256];

    int tok   = tokens[(size_t)b * L + l];
    float c   = g_ctable[tok];
    float score = (c > 0.f) ? c : -1e9f;
    int   cnt = (tok != 0) ? 1 : 0;

    float m = score, sc = c; int cn = cnt;
#pragma unroll
    for (int o = 16; o; o >>= 1) {
        m  = fmaxf(m, __shfl_xor_sync(0xffffffffu, m, o));
        sc += __shfl_xor_sync(0xffffffffu, sc, o);
        cn += __shfl_xor_sync(0xffffffffu, cn, o);
    }
    if (lane == 0) { red_m[wid] = m; red_s[wid] = sc; red_n[wid] = cn; }
    __syncthreads();
    if (l == 0) {
        float M = red_m[0], S = red_s[0]; int N = red_n[0];
#pragma unroll
        for (int i = 1; i < 8; i++) { M = fmaxf(M, red_m[i]); S += red_s[i]; N += red_n[i]; }
        bc_max = M;
        bc_cs  = S / ((float)N + 1e-5f);
    }
    __syncthreads();

    float M  = bc_max;
    float cs = bc_cs;
    float e  = expf(score - M);

    float se = e;
#pragma unroll
    for (int o = 16; o; o >>= 1) se += __shfl_xor_sync(0xffffffffu, se, o);
    if (lane == 0) red_s[wid] = se;
    __syncthreads();
    if (l == 0) {
        float D = red_s[0];
#pragma unroll
        for (int i = 1; i < 8; i++) D += red_s[i];
        bc_den = D;
    }
    __syncthreads();

    float a = e / bc_den;
    attn[(size_t)b * L + l] = a;
    if (l == 0) cscore[b] = cs;

    bool gate = cs > 1e-4f;
    if (gate) {
        bool act = (e > 0.f);
        unsigned mask = __ballot_sync(0xffffffffu, act);
        if (lane == 0) s_woff[wid] = __popc(mask);
        __syncthreads();
        if (l == 0) {
            int o = 0;
#pragma unroll
            for (int i = 0; i < 8; i++) { int tt = s_woff[i]; s_woff[i] = o; o += tt; }
            s_n = o;
        }
        __syncthreads();
        if (act) {
            int pos = s_woff[wid] + __popc(mask & ((1u << lane) - 1u));
            s_tok[pos] = tok;
            s_w[pos]   = a;
        }
        __syncthreads();
        int n = s_n;
        for (int j = l; j < E; j += 256) {
            float z = 0.f;
            for (int i = 0; i < n; i++)
                z = fmaf(s_w[i], w_emb[(size_t)s_tok[i] * E + j], z);
            enc[(size_t)b * E + j] = z;
        }
    } else {
        for (int j = l; j < E; j += 256)
            enc[(size_t)b * E + j] = 0.f;
    }
}

// ---------------- launch ----------------
extern "C" void kernel_launch(void* const* d_in, const int* in_sizes, int n_in,
                              void* d_out, int out_size) {
    const int*   inputs = (const int*)d_in[0];     // [B, L]
    const float* w_emb  = (const float*)d_in[1];   // [V, E]
    const float* a_emb  = (const float*)d_in[2];   // [A, E]
    const float* a_w    = (const float*)d_in[3];   // [A]

    int BL = in_sizes[0];
    int A  = in_sizes[3];
    int E  = in_sizes[2] / A;        // 300
    int V  = in_sizes[1] / E;        // 50000
    int L  = 256;
    int B  = BL / L;                 // 1024

    static bool attr_set = false;
    if (!attr_set) {
        cudaFuncSetAttribute(vocab_mma, cudaFuncAttributeMaxDynamicSharedMemorySize, SMEM_TOT);
        attr_set = true;
    }

    vocab_mma<<<(V + 127) / 128, 256, SMEM_TOT>>>(w_emb, a_emb, a_w, V);

    float* out    = (float*)d_out;
    float* enc    = out;                                   // [B, E]
    float* attn   = out + (size_t)B * E;                   // [B, L]
    float* cscore = out + (size_t)B * E + (size_t)B * L;   // [B]
    row_kernel<<<B, 256>>>(inputs, w_emb, enc, attn, cscore, L, E);
}